// round 8
// baseline (speedup 1.0000x reference)
#include <cuda_runtime.h>
#include <math.h>

#define Bb 16
#define Nn 4096
#define Dd 64
#define Ss 1024
#define Kk 32
#define Mm (Bb*Ss*Kk)        // 524288 grouped points

typedef unsigned long long ull;

// ------------------------- device scratch (no allocs allowed) --------------
__device__ int    g_knn[Mm];
__device__ float  g_y0[Mm*64];          // [M,64]
__device__ float  g_y1[Mm*64];          // [M,64]
__device__ float  g_parts[4096*128];    // per-block channel sums
__device__ float  g_partq[4096*128];    // per-block channel sumsq
__device__ float  g_gmax[Bb*Ss*128];    // per-group raw max (pre-BN)
__device__ float  g_scale[128];
__device__ float  g_shift[128];
__device__ ull    g_Wdup[16576];        // dup'd W0 [67*64] | W1 [64*64] | W2 [64*128]

// ------------------------- f32x2 helpers -----------------------------------
__device__ __forceinline__ ull f2fma(ull a, ull b, ull c) {
    ull d;
    asm("fma.rn.f32x2 %0, %1, %2, %3;" : "=l"(d) : "l"(a), "l"(b), "l"(c));
    return d;
}
__device__ __forceinline__ ull f2add(ull a, ull b) {
    ull d;
    asm("add.rn.f32x2 %0, %1, %2;" : "=l"(d) : "l"(a), "l"(b));
    return d;
}
__device__ __forceinline__ ull f2mul(ull a, ull b) {
    ull d;
    asm("mul.rn.f32x2 %0, %1, %2;" : "=l"(d) : "l"(a), "l"(b));
    return d;
}
__device__ __forceinline__ ull f2dup(float v) {
    ull d;
    asm("mov.b64 %0, {%1, %1};" : "=l"(d) : "f"(v));
    return d;
}
__device__ __forceinline__ ull f2pack(float lo, float hi) {
    ull d;
    asm("mov.b64 %0, {%1, %2};" : "=l"(d) : "f"(lo), "f"(hi));
    return d;
}
__device__ __forceinline__ void f2unpack(ull v, float& lo, float& hi) {
    asm("mov.b64 {%0, %1}, %2;" : "=f"(lo), "=f"(hi) : "l"(v));
}

// v2 packing: 64-channel row = 4 sections x 16 ull; section s, lane j holds
// channels (8j+2s, 8j+2s+1) -> each B load reads contiguous 128B.
__device__ __forceinline__ int wpos64_v2(int o) {
    return ((o & 7) >> 1) * 16 + (o >> 3) * 2 + (o & 1);
}

// monotone float->uint map (order-preserving for all signs)
__device__ __forceinline__ unsigned mono(float f) {
    unsigned b = __float_as_uint(f);
    return b ^ (unsigned)(((int)b >> 31) | 0x80000000);
}

// ============================================================================
// 0) prep: duplicate weights into f32x2 v2-packed layout (launch slot 0)
// ============================================================================
__global__ void prep_kernel(const float* __restrict__ W0,
                            const float* __restrict__ W1,
                            const float* __restrict__ W2)
{
    const int t = blockIdx.x * 256 + threadIdx.x;
    const int stride = gridDim.x * 256;
    for (int i = t; i < 4288; i += stride) {      // W0: [o=64][c=67]
        int c = i >> 6, o = i & 63;
        g_Wdup[c * 64 + wpos64_v2(o)] = f2dup(W0[o * 67 + c]);
    }
    for (int i = t; i < 4096; i += stride) {      // W1: [o=64][c=64]
        int c = i >> 6, o = i & 63;
        g_Wdup[4288 + c * 64 + wpos64_v2(o)] = f2dup(W1[o * 64 + c]);
    }
    for (int i = t; i < 8192; i += stride) {      // W2: [o=128][c=64]
        int c = i >> 7, o = i & 127;
        int blk = o >> 6, oo = o & 63;
        g_Wdup[8384 + c * 128 + blk * 64 + wpos64_v2(oo)] = f2dup(W2[o * 64 + c]);
    }
}

// ============================================================================
// 1) FPS: one block/batch, 512 threads x 8 points, f32x2 distance math
//    (lane-wise bit-identical to scalar rn ops). Single barrier/iteration.
//    argmax tie -> lowest index, matching jnp.argmax.
// ============================================================================
__global__ __launch_bounds__(512, 1)
void fps_kernel(const float* __restrict__ xyz, float* __restrict__ out_xyz)
{
    extern __shared__ float4 sp[];                 // [Nn]
    ull* s_key = (ull*)(sp + Nn);                  // [2][16]

    const int b = blockIdx.x, tid = threadIdx.x;
    const int lane = tid & 31, warp = tid >> 5;
    const float* base = xyz + (size_t)b * Nn * 3;

    // pair j holds points (tid + 2j*512, tid + (2j+1)*512)
    ull px2[4], py2[4], pz2[4];
    float dist[8];
#pragma unroll
    for (int j = 0; j < 4; j++) {
        int plo = tid + (2*j) * 512, phi = tid + (2*j+1) * 512;
        float Xl = base[plo*3+0], Yl = base[plo*3+1], Zl = base[plo*3+2];
        float Xh = base[phi*3+0], Yh = base[phi*3+1], Zh = base[phi*3+2];
        sp[plo] = make_float4(Xl, Yl, Zl, 0.f);
        sp[phi] = make_float4(Xh, Yh, Zh, 0.f);
        px2[j] = f2pack(Xl, Xh); py2[j] = f2pack(Yl, Yh); pz2[j] = f2pack(Zl, Zh);
        dist[2*j] = 1e10f; dist[2*j+1] = 1e10f;
    }
    __syncthreads();

    int far = 0;
    float* ob = out_xyz + (size_t)b * Ss * 3;
    for (int it = 0; it < Ss; ++it) {
        float4 c = sp[far];
        if (tid == 0) { ob[it*3+0] = c.x; ob[it*3+1] = c.y; ob[it*3+2] = c.z; }
        ull ncx = f2dup(-c.x), ncy = f2dup(-c.y), ncz = f2dup(-c.z);

        unsigned u[8];
#pragma unroll
        for (int j = 0; j < 4; j++) {
            ull dx = f2add(px2[j], ncx);     // == a - b exactly
            ull dy = f2add(py2[j], ncy);
            ull dz = f2add(pz2[j], ncz);
            ull s  = f2add(f2add(f2mul(dx,dx), f2mul(dy,dy)), f2mul(dz,dz));
            float lo, hi; f2unpack(s, lo, hi);
            float dl = fminf(dist[2*j], lo);
            float dh = fminf(dist[2*j+1], hi);
            dist[2*j] = dl; dist[2*j+1] = dh;
            u[2*j] = __float_as_uint(dl);    // d >= 0: uint order == float order
            u[2*j+1] = __float_as_uint(dh);
        }
        // tree argmax over 8, strict > keeps lower slot (lower index) on ties
        unsigned v[4], jx[4];
#pragma unroll
        for (int j = 0; j < 4; j++) {
            bool g = u[2*j+1] > u[2*j];
            v[j] = g ? u[2*j+1] : u[2*j];
            jx[j] = 2*j + (g ? 1u : 0u);
        }
        bool ga = v[1] > v[0];
        unsigned va = ga ? v[1] : v[0], ja = ga ? jx[1] : jx[0];
        bool gb = v[3] > v[2];
        unsigned vb2 = gb ? v[3] : v[2], jb = gb ? jx[3] : jx[2];
        bool gc = vb2 > va;
        unsigned bb = gc ? vb2 : va, jj = gc ? jb : ja;
        int bi = tid + (int)jj * 512;

        unsigned mv = __reduce_max_sync(0xffffffffu, bb);
        int ci = (bb == mv) ? bi : 0x7fffffff;
        int mi = __reduce_min_sync(0xffffffffu, ci);
        if (lane == 0)
            s_key[(it & 1) * 16 + warp] = ((ull)mv << 32) | (unsigned)(0x7fffffff - mi);
        __syncthreads();

        ull k = s_key[(it & 1) * 16 + (lane & 15)];   // lanes 16-31 duplicate
        unsigned hv = (unsigned)(k >> 32), lv = (unsigned)k;
        unsigned mh = __reduce_max_sync(0xffffffffu, hv);
        unsigned ml = __reduce_max_sync(0xffffffffu, (hv == mh) ? lv : 0u);
        far = 0x7fffffff - (int)ml;
    }
}

// ============================================================================
// 2) KNN: one WARP per query, single pass. 32 lanes hold the running top-32
//    (key, idx); threshold via REDUX; inserts warp-collective. Output order
//    is arbitrary (downstream max-pool/BN are order-invariant).
// ============================================================================
__global__ __launch_bounds__(512, 1)
void knn_kernel(const float* __restrict__ xyz, const float* __restrict__ samp)
{
    extern __shared__ float4 sq[];
    const int b = blockIdx.y, t = threadIdx.x;
    const int lane = t & 31, w = t >> 5;
    const float* base = xyz + (size_t)b * Nn * 3;
    for (int j = t; j < Nn; j += 512) {
        float x = base[j*3], y = base[j*3+1], z = base[j*3+2];
        sq[j] = make_float4(x, y, z, fmaf(x,x, fmaf(y,y, z*z)));
    }
    __syncthreads();

    const int q = b * Ss + blockIdx.x * 16 + w;
    float qx = samp[q*3], qy = samp[q*3+1], qz = samp[q*3+2];
    float ax = -2.0f*qx, ay = -2.0f*qy, az = -2.0f*qz;

    float4 p0 = sq[lane];
    unsigned held = mono(fmaf(az, p0.z, fmaf(ay, p0.y, fmaf(ax, p0.x, p0.w))));
    int held_idx = lane;
    unsigned thr = __reduce_max_sync(0xffffffffu, held);

#pragma unroll 1
    for (int step = 1; step < Nn / 32; step++) {
        float4 p = sq[step * 32 + lane];
        unsigned u = mono(fmaf(az, p.z, fmaf(ay, p.y, fmaf(ax, p.x, p.w))));
        unsigned m = __ballot_sync(0xffffffffu, u < thr);
        while (m) {
            int src = __ffs(m) - 1;
            unsigned uc = __shfl_sync(0xffffffffu, u, src);
            if (uc < thr) {
                unsigned vb = __ballot_sync(0xffffffffu, held == thr);
                int victim = __ffs(vb) - 1;
                if (lane == victim) { held = uc; held_idx = step * 32 + src; }
                thr = __reduce_max_sync(0xffffffffu, held);
            }
            m &= m - 1;
            m &= __ballot_sync(0xffffffffu, u < thr);
        }
    }
    g_knn[(size_t)q * Kk + lane] = held_idx;
}

// ============================================================================
// 3) MLP GEMM (f32x2): 128 threads, block tile 128 pts x 64 ch,
//    thread tile 8 pts x 8 ch. W read via __ldg (L1-resident, no smem tile).
//    Fused BN stats; layer 2 also fuses the per-group max-pool.
// ============================================================================
template <int CIN, int LAYER>
__global__ __launch_bounds__(128, 4)
void gemm_kernel(const float* __restrict__ fea,
                 const float* __restrict__ xyz,
                 const float* __restrict__ samp)
{
    extern __shared__ float smem[];
    float* Xs    = smem;                         // [CIN][128]
    int*   s_idx = (int*)(smem + CIN * 128);     // [128]

    const int t    = threadIdx.x;
    const int lane = t & 31, w = t >> 5;
    const int m0   = blockIdx.x * 128;
    const int n0   = blockIdx.y * 64;
    const int chb  = t & 7;                      // channel-octet lane
    const int pt   = (t >> 3) << 3;              // point group (8 pts)

    // ---- load X tile ----
    if (LAYER == 0) {
        {
            int m = m0 + t;
            int g = m >> 5;
            int idx = g_knn[m];
            int bz = g >> 10;
            int row = bz * Nn + idx;
            float sx0 = samp[g*3], sy0 = samp[g*3+1], sz0 = samp[g*3+2];
            Xs[0*128 + t] = xyz[row*3+0] - sx0;
            Xs[1*128 + t] = xyz[row*3+1] - sy0;
            Xs[2*128 + t] = xyz[row*3+2] - sz0;
            s_idx[t] = row;
        }
        __syncthreads();
        {
            const float4* src = (const float4*)(fea + (size_t)s_idx[t] * Dd);
#pragma unroll
            for (int qq = 0; qq < 16; qq++) {
                float4 v = src[qq];
                int c = 3 + qq * 4;
                Xs[(c+0)*128 + t] = v.x;
                Xs[(c+1)*128 + t] = v.y;
                Xs[(c+2)*128 + t] = v.z;
                Xs[(c+3)*128 + t] = v.w;
            }
        }
    } else {
        const float* Xin = (LAYER == 1) ? g_y0 : g_y1;
        const float4* src = (const float4*)(Xin + (size_t)(m0 + t) * 64);
#pragma unroll
        for (int qq = 0; qq < 16; qq++) {
            float4 v = src[qq];
            int c = qq * 4;
            Xs[(c+0)*128 + t] = fmaxf(fmaf(v.x, g_scale[c+0], g_shift[c+0]), 0.f);
            Xs[(c+1)*128 + t] = fmaxf(fmaf(v.y, g_scale[c+1], g_shift[c+1]), 0.f);
            Xs[(c+2)*128 + t] = fmaxf(fmaf(v.z, g_scale[c+2], g_shift[c+2]), 0.f);
            Xs[(c+3)*128 + t] = fmaxf(fmaf(v.w, g_scale[c+3], g_shift[c+3]), 0.f);
        }
    }
    __syncthreads();

    // ---- compute: thread -> points [pt..pt+7], channels [8*chb..8*chb+7] ----
    ull acc[4][8];
#pragma unroll
    for (int i = 0; i < 4; i++)
#pragma unroll
        for (int j = 0; j < 8; j++) acc[i][j] = 0ull;

    // W base in global (v2-packed, L1 resident)
    const ulonglong2* Wg = (const ulonglong2*)
        (g_Wdup + ((LAYER == 0) ? 0 : (LAYER == 1) ? 4288 : 8384));
    const int wrow = (LAYER == 2) ? 64 : 32;           // ull2 per cin row
    const int woff = (LAYER == 2) ? (n0 >> 1) : 0;

#pragma unroll 4
    for (int c = 0; c < CIN; c++) {
        ulonglong2 A0 = *(const ulonglong2*)(Xs + c * 128 + pt);
        ulonglong2 A1 = *(const ulonglong2*)(Xs + c * 128 + pt + 4);
#pragma unroll
        for (int s = 0; s < 4; s++) {
            ulonglong2 Bs = __ldg(&Wg[c * wrow + woff + s * 8 + chb]);
            acc[0][2*s  ] = f2fma(A0.x, Bs.x, acc[0][2*s  ]);
            acc[0][2*s+1] = f2fma(A0.x, Bs.y, acc[0][2*s+1]);
            acc[1][2*s  ] = f2fma(A0.y, Bs.x, acc[1][2*s  ]);
            acc[1][2*s+1] = f2fma(A0.y, Bs.y, acc[1][2*s+1]);
            acc[2][2*s  ] = f2fma(A1.x, Bs.x, acc[2][2*s  ]);
            acc[2][2*s+1] = f2fma(A1.x, Bs.y, acc[2][2*s+1]);
            acc[3][2*s  ] = f2fma(A1.y, Bs.x, acc[3][2*s  ]);
            acc[3][2*s+1] = f2fma(A1.y, Bs.y, acc[3][2*s+1]);
        }
    }

    // ---- store Y + fused stats ----
    float s8[8] = {0,0,0,0,0,0,0,0}, q8[8] = {0,0,0,0,0,0,0,0}, m8[8];
#pragma unroll
    for (int j = 0; j < 8; j++) m8[j] = -1e30f;

    float* Y = (LAYER == 0) ? g_y0 : g_y1;
#pragma unroll
    for (int i = 0; i < 4; i++) {
        float lo[8], hi[8];
#pragma unroll
        for (int j = 0; j < 8; j++) {
            f2unpack(acc[i][j], lo[j], hi[j]);
            s8[j] += lo[j] + hi[j];
            q8[j]  = fmaf(lo[j], lo[j], fmaf(hi[j], hi[j], q8[j]));
            if (LAYER == 2) m8[j] = fmaxf(m8[j], fmaxf(lo[j], hi[j]));
        }
        if (LAYER != 2) {
            size_t r0 = (size_t)(m0 + pt + 2*i) * 64 + chb * 8;
            *(float4*)(Y + r0)      = make_float4(lo[0], lo[1], lo[2], lo[3]);
            *(float4*)(Y + r0 + 4)  = make_float4(lo[4], lo[5], lo[6], lo[7]);
            *(float4*)(Y + r0 + 64) = make_float4(hi[0], hi[1], hi[2], hi[3]);
            *(float4*)(Y + r0 + 68) = make_float4(hi[4], hi[5], hi[6], hi[7]);
        }
    }

    // in-warp reduce across the 4 point-groups (lanes +16, +8)
#pragma unroll
    for (int j = 0; j < 8; j++) {
        s8[j] += __shfl_down_sync(0xffffffffu, s8[j], 16);
        s8[j] += __shfl_down_sync(0xffffffffu, s8[j], 8);
        q8[j] += __shfl_down_sync(0xffffffffu, q8[j], 16);
        q8[j] += __shfl_down_sync(0xffffffffu, q8[j], 8);
        if (LAYER == 2) {
            m8[j] = fmaxf(m8[j], __shfl_down_sync(0xffffffffu, m8[j], 16));
            m8[j] = fmaxf(m8[j], __shfl_down_sync(0xffffffffu, m8[j], 8));
        }
    }
    __syncthreads();   // done with Xs — reuse smem as reduction scratch
    float* Ssm = smem;           // [4][64]
    float* Sqm = smem + 256;     // [4][64]
    if (lane < 8) {
#pragma unroll
        for (int j = 0; j < 8; j++) {
            Ssm[w * 64 + lane * 8 + j] = s8[j];
            Sqm[w * 64 + lane * 8 + j] = q8[j];
        }
        if (LAYER == 2) {
            float* gm = g_gmax + ((size_t)(m0 >> 5) + w) * 128 + n0 + lane * 8;
            *(float4*)(gm)     = make_float4(m8[0], m8[1], m8[2], m8[3]);
            *(float4*)(gm + 4) = make_float4(m8[4], m8[5], m8[6], m8[7]);
        }
    }
    __syncthreads();
    if (t < 64) {
        float vs = 0.f, vq = 0.f;
#pragma unroll
        for (int ww = 0; ww < 4; ww++) {
            vs += Ssm[ww * 64 + t];
            vq += Sqm[ww * 64 + t];
        }
        size_t pi = (LAYER == 2) ? ((size_t)blockIdx.x * 128 + n0 + t)
                                 : ((size_t)blockIdx.x * 64 + t);
        g_parts[pi] = vs;
        g_partq[pi] = vq;
    }
}

// ============================================================================
// 4) finalize BN: one block per channel, double accumulation.
// ============================================================================
template <int C>
__global__ __launch_bounds__(256)
void finalize_kernel(const float* __restrict__ g, const float* __restrict__ be)
{
    __shared__ double shs[256], shq[256];
    const int c = blockIdx.x, t = threadIdx.x;
    double s = 0.0, q = 0.0;
    for (int i = t; i < 4096; i += 256) {
        s += (double)g_parts[(size_t)i * C + c];
        q += (double)g_partq[(size_t)i * C + c];
    }
    shs[t] = s; shq[t] = q;
    __syncthreads();
    for (int o = 128; o; o >>= 1) {
        if (t < o) { shs[t] += shs[t+o]; shq[t] += shq[t+o]; }
        __syncthreads();
    }
    if (t == 0) {
        double mean = shs[0] / (double)Mm;
        double var  = shq[0] / (double)Mm - mean * mean;
        float sc = g[c] * (1.0f / sqrtf((float)var + 1e-5f));
        g_scale[c] = sc;
        g_shift[c] = fmaf(-(float)mean, sc, be[c]);
    }
}

// ============================================================================
// 5) output: BN affine + ReLU applied to raw group maxes (scale > 0).
// ============================================================================
__global__ __launch_bounds__(256)
void maxout_kernel(float* __restrict__ feats)
{
    int i = blockIdx.x * 256 + threadIdx.x;
    int c = i & 127;
    feats[i] = fmaxf(fmaf(g_gmax[i], g_scale[c], g_shift[c]), 0.f);
}

// ============================================================================
extern "C" void kernel_launch(void* const* d_in, const int* in_sizes, int n_in,
                              void* d_out, int out_size)
{
    const float* xyz = (const float*)d_in[0];
    const float* fea = (const float*)d_in[1];
    const float* W0  = (const float*)d_in[2];
    const float* g0  = (const float*)d_in[4];
    const float* be0 = (const float*)d_in[5];
    const float* W1  = (const float*)d_in[6];
    const float* g1  = (const float*)d_in[8];
    const float* be1 = (const float*)d_in[9];
    const float* W2  = (const float*)d_in[10];
    const float* g2  = (const float*)d_in[12];
    const float* be2 = (const float*)d_in[13];

    float* out   = (float*)d_out;
    float* samp  = out;                    // [B,S,3]
    float* feats = out + Bb * Ss * 3;      // [B,S,128]

    const int fps_smem = Nn * 16 + 2 * 16 * 8 + 16;
    const int knn_smem = Nn * 16;
    const int g0_smem  = 67 * 128 * 4 + 512;
    const int g1_smem  = 64 * 128 * 4 + 512;

    cudaFuncSetAttribute(fps_kernel, cudaFuncAttributeMaxDynamicSharedMemorySize, fps_smem);
    cudaFuncSetAttribute(knn_kernel, cudaFuncAttributeMaxDynamicSharedMemorySize, knn_smem);
    cudaFuncSetAttribute(gemm_kernel<67,0>, cudaFuncAttributeMaxDynamicSharedMemorySize, g0_smem);
    cudaFuncSetAttribute(gemm_kernel<64,1>, cudaFuncAttributeMaxDynamicSharedMemorySize, g1_smem);
    cudaFuncSetAttribute(gemm_kernel<64,2>, cudaFuncAttributeMaxDynamicSharedMemorySize, g1_smem);

    // slot 0: weight prep; fps(1), knn(2) -> gemm0 lands on capture slot 3
    prep_kernel<<<16, 256>>>(W0, W1, W2);

    fps_kernel<<<Bb, 512, fps_smem>>>(xyz, samp);
    knn_kernel<<<dim3(Ss/16, Bb), 512, knn_smem>>>(xyz, samp);

    gemm_kernel<67,0><<<Mm/128, 128, g0_smem>>>(fea, xyz, samp);
    finalize_kernel<64><<<64, 256>>>(g0, be0);

    gemm_kernel<64,1><<<Mm/128, 128, g1_smem>>>(nullptr, nullptr, nullptr);
    finalize_kernel<64><<<64, 256>>>(g1, be1);

    gemm_kernel<64,2><<<dim3(Mm/128, 2), 128, g1_smem>>>(nullptr, nullptr, nullptr);
    finalize_kernel<128><<<128, 256>>>(g2, be2);

    maxout_kernel<<<(Bb*Ss*128)/256, 256>>>(feats);
}

// round 11
// speedup vs baseline: 1.2103x; 1.2103x over previous
#include <cuda_runtime.h>
#include <cuda_bf16.h>
#include <math.h>

#define Bb 16
#define Nn 4096
#define Dd 64
#define Ss 1024
#define Kk 32
#define Mm (Bb*Ss*Kk)

typedef unsigned long long ull;
typedef unsigned int u32;
typedef unsigned short u16;

__device__ int    g_knn[Mm];
__device__ float  g_y0[Mm*64];
__device__ float  g_y1[Mm*64];
__device__ float  g_parts[4096*128];
__device__ float  g_partq[4096*128];
__device__ float  g_gmax[Bb*Ss*128];
__device__ float  g_scale[128];
__device__ float  g_shift[128];
__device__ __align__(16) u16 g_Bh[3][8192];  // bf16 hi W tiles [n][k], swizzled rows
__device__ __align__(16) u16 g_Bl[3][8192];  // bf16 lo
__device__ float  g_W0xyz[192];              // [3][64]

// ---- f32x2 helpers (fps) ----
__device__ __forceinline__ ull f2add(ull a, ull b){ ull d; asm("add.rn.f32x2 %0,%1,%2;":"=l"(d):"l"(a),"l"(b)); return d; }
__device__ __forceinline__ ull f2mul(ull a, ull b){ ull d; asm("mul.rn.f32x2 %0,%1,%2;":"=l"(d):"l"(a),"l"(b)); return d; }
__device__ __forceinline__ ull f2dup(float v){ ull d; asm("mov.b64 %0,{%1,%1};":"=l"(d):"f"(v)); return d; }
__device__ __forceinline__ ull f2pack(float l, float h){ ull d; asm("mov.b64 %0,{%1,%2};":"=l"(d):"f"(l),"f"(h)); return d; }
__device__ __forceinline__ void f2unpack(ull v, float& l, float& h){ asm("mov.b64 {%0,%1},%2;":"=f"(l),"=f"(h):"l"(v)); }
__device__ __forceinline__ unsigned mono(float f){ unsigned b=__float_as_uint(f); return b ^ (unsigned)(((int)b>>31)|0x80000000); }

__device__ __forceinline__ u32 bfpack(float a, float b){
    __nv_bfloat16 ha=__float2bfloat16(a), hb=__float2bfloat16(b);
    return (u32)(*(u16*)&ha) | ((u32)(*(u16*)&hb)<<16);
}

#define MMA_BF16(c, a, b0v, b1v) \
    asm volatile("mma.sync.aligned.m16n8k16.row.col.f32.bf16.bf16.f32 " \
        "{%0,%1,%2,%3},{%4,%5,%6,%7},{%8,%9},{%0,%1,%2,%3};" \
        : "+f"((c)[0]),"+f"((c)[1]),"+f"((c)[2]),"+f"((c)[3]) \
        : "r"((a)[0]),"r"((a)[1]),"r"((a)[2]),"r"((a)[3]), "r"(b0v),"r"(b1v))

// ============================================================================
// 0) prep: split W into bf16 hi/lo, rows [n][k] 128B with XOR swizzle applied
// ============================================================================
__device__ __forceinline__ void wsplit(float x, u16* H, u16* L, int o, int k){
    __nv_bfloat16 h = __float2bfloat16(x);
    float r = x - __bfloat162float(h);
    __nv_bfloat16 l = __float2bfloat16(r);
    u32 off = (u32)(o*128) + (((u32)(k*2)) ^ (u32)((o&7)<<4));
    H[off>>1] = *(u16*)&h;  L[off>>1] = *(u16*)&l;
}
__global__ void prep_kernel(const float* __restrict__ W0, const float* __restrict__ W1,
                            const float* __restrict__ W2){
    int t = blockIdx.x*256+threadIdx.x, st = gridDim.x*256;
    for (int i=t;i<4096;i+=st){ int o=i>>6,k=i&63; wsplit(W0[o*67+3+k], g_Bh[0], g_Bl[0], o,k); }
    for (int i=t;i<4096;i+=st){ int o=i>>6,k=i&63; wsplit(W1[o*64+k],   g_Bh[1], g_Bl[1], o,k); }
    for (int i=t;i<8192;i+=st){ int o=i>>6,k=i&63; wsplit(W2[o*64+k],   g_Bh[2], g_Bl[2], o,k); }
    for (int i=t;i<192;i+=st){ int j=i>>6,o=i&63; g_W0xyz[j*64+o] = W0[o*67+j]; }
}

// ============================================================================
// 1) FPS (unchanged — bit-exact, single barrier/iter)
// ============================================================================
__global__ __launch_bounds__(512, 1)
void fps_kernel(const float* __restrict__ xyz, float* __restrict__ out_xyz)
{
    extern __shared__ float4 sp[];
    ull* s_key = (ull*)(sp + Nn);
    const int b = blockIdx.x, tid = threadIdx.x;
    const int lane = tid & 31, warp = tid >> 5;
    const float* base = xyz + (size_t)b * Nn * 3;

    ull px2[4], py2[4], pz2[4];
    float dist[8];
#pragma unroll
    for (int j = 0; j < 4; j++) {
        int plo = tid + (2*j)*512, phi = tid + (2*j+1)*512;
        float Xl = base[plo*3+0], Yl = base[plo*3+1], Zl = base[plo*3+2];
        float Xh = base[phi*3+0], Yh = base[phi*3+1], Zh = base[phi*3+2];
        sp[plo] = make_float4(Xl, Yl, Zl, 0.f);
        sp[phi] = make_float4(Xh, Yh, Zh, 0.f);
        px2[j] = f2pack(Xl, Xh); py2[j] = f2pack(Yl, Yh); pz2[j] = f2pack(Zl, Zh);
        dist[2*j] = 1e10f; dist[2*j+1] = 1e10f;
    }
    __syncthreads();

    int far = 0;
    float* ob = out_xyz + (size_t)b * Ss * 3;
    for (int it = 0; it < Ss; ++it) {
        float4 c = sp[far];
        if (tid == 0) { ob[it*3+0]=c.x; ob[it*3+1]=c.y; ob[it*3+2]=c.z; }
        ull ncx = f2dup(-c.x), ncy = f2dup(-c.y), ncz = f2dup(-c.z);
        unsigned u[8];
#pragma unroll
        for (int j = 0; j < 4; j++) {
            ull dx = f2add(px2[j], ncx), dy = f2add(py2[j], ncy), dz = f2add(pz2[j], ncz);
            ull s = f2add(f2add(f2mul(dx,dx), f2mul(dy,dy)), f2mul(dz,dz));
            float lo, hi; f2unpack(s, lo, hi);
            float dl = fminf(dist[2*j], lo), dh = fminf(dist[2*j+1], hi);
            dist[2*j] = dl; dist[2*j+1] = dh;
            u[2*j] = __float_as_uint(dl); u[2*j+1] = __float_as_uint(dh);
        }
        unsigned v[4], jx[4];
#pragma unroll
        for (int j = 0; j < 4; j++) {
            bool g = u[2*j+1] > u[2*j];
            v[j] = g ? u[2*j+1] : u[2*j];
            jx[j] = 2*j + (g ? 1u : 0u);
        }
        bool ga = v[1] > v[0];
        unsigned va = ga ? v[1] : v[0], ja = ga ? jx[1] : jx[0];
        bool gb = v[3] > v[2];
        unsigned vb2 = gb ? v[3] : v[2], jb = gb ? jx[3] : jx[2];
        bool gc = vb2 > va;
        unsigned bb = gc ? vb2 : va, jj = gc ? jb : ja;
        int bi = tid + (int)jj * 512;

        unsigned mv = __reduce_max_sync(0xffffffffu, bb);
        int ci = (bb == mv) ? bi : 0x7fffffff;
        int mi = __reduce_min_sync(0xffffffffu, ci);
        if (lane == 0)
            s_key[(it&1)*16 + warp] = ((ull)mv << 32) | (unsigned)(0x7fffffff - mi);
        __syncthreads();
        ull k = s_key[(it&1)*16 + (lane & 15)];
        unsigned hv = (unsigned)(k >> 32), lv = (unsigned)k;
        unsigned mh = __reduce_max_sync(0xffffffffu, hv);
        unsigned ml = __reduce_max_sync(0xffffffffu, (hv == mh) ? lv : 0u);
        far = 0x7fffffff - (int)ml;
    }
}

// ============================================================================
// 2) KNN (unchanged): warp per query, single pass
// ============================================================================
__global__ __launch_bounds__(512, 1)
void knn_kernel(const float* __restrict__ xyz, const float* __restrict__ samp)
{
    extern __shared__ float4 sq[];
    const int b = blockIdx.y, t = threadIdx.x;
    const int lane = t & 31, w = t >> 5;
    const float* base = xyz + (size_t)b * Nn * 3;
    for (int j = t; j < Nn; j += 512) {
        float x = base[j*3], y = base[j*3+1], z = base[j*3+2];
        sq[j] = make_float4(x, y, z, fmaf(x,x, fmaf(y,y, z*z)));
    }
    __syncthreads();

    const int q = b * Ss + blockIdx.x * 16 + w;
    float qx = samp[q*3], qy = samp[q*3+1], qz = samp[q*3+2];
    float ax = -2.0f*qx, ay = -2.0f*qy, az = -2.0f*qz;

    float4 p0 = sq[lane];
    unsigned held = mono(fmaf(az, p0.z, fmaf(ay, p0.y, fmaf(ax, p0.x, p0.w))));
    int held_idx = lane;
    unsigned thr = __reduce_max_sync(0xffffffffu, held);

#pragma unroll 1
    for (int step = 1; step < Nn/32; step++) {
        float4 p = sq[step*32 + lane];
        unsigned u = mono(fmaf(az, p.z, fmaf(ay, p.y, fmaf(ax, p.x, p.w))));
        unsigned m = __ballot_sync(0xffffffffu, u < thr);
        while (m) {
            int src = __ffs(m) - 1;
            unsigned uc = __shfl_sync(0xffffffffu, u, src);
            if (uc < thr) {
                unsigned vb = __ballot_sync(0xffffffffu, held == thr);
                int victim = __ffs(vb) - 1;
                if (lane == victim) { held = uc; held_idx = step*32 + src; }
                thr = __reduce_max_sync(0xffffffffu, held);
            }
            m &= m - 1;
            m &= __ballot_sync(0xffffffffu, u < thr);
        }
    }
    g_knn[(size_t)q * Kk + lane] = held_idx;
}

// ============================================================================
// 3) MLP layer via mma.sync bf16-split emulated fp32.
//    Block: 128 pts x 64 ch, 4 warps (warp = 32 pts). 12 MMAs/(Mtile,Ntile).
//    FIX vs R10: fragment coords use LANE, not block-thread id.
// ============================================================================
template <int LAYER>
__global__ __launch_bounds__(128)
void mma_kernel(const float* __restrict__ fea, const float* __restrict__ xyz,
                const float* __restrict__ samp)
{
    extern __shared__ __align__(16) char sm[];
    const int A_HI=0, A_LO=16384, B_HI=32768, B_LO=40960, DX=49152, WX=50688;
    const int t = threadIdx.x, lane = t&31, w = t>>5;
    const int m0p = blockIdx.x*128;
    const int n0  = (LAYER==2) ? blockIdx.y*64 : 0;

    // ---- B tiles -> smem (plain copy; swizzle already applied) ----
    {
        const uint4* BH = (const uint4*)(g_Bh[LAYER]) + n0*8;
        const uint4* BL = (const uint4*)(g_Bl[LAYER]) + n0*8;
        uint4* dh = (uint4*)(sm+B_HI); uint4* dl = (uint4*)(sm+B_LO);
#pragma unroll
        for (int i = 0; i < 4; i++) { dh[t+128*i] = BH[t+128*i]; dl[t+128*i] = BL[t+128*i]; }
    }

    // ---- X row load (+BN-ReLU for layers 1/2) ----
    float xv[64];
    if (LAYER == 0) {
        int m = m0p + t, g = m>>5, idx = g_knn[m];
        int row = (g>>10)*Nn + idx;
        float dx = xyz[row*3+0]-samp[g*3+0];
        float dy = xyz[row*3+1]-samp[g*3+1];
        float dz = xyz[row*3+2]-samp[g*3+2];
        ((float*)(sm+DX))[t] = dx; ((float*)(sm+DX))[128+t] = dy; ((float*)(sm+DX))[256+t] = dz;
        for (int i=t;i<192;i+=128) ((float*)(sm+WX))[i] = g_W0xyz[i];
        const float4* src = (const float4*)(fea + (size_t)row*Dd);
#pragma unroll
        for (int qq=0; qq<16; qq++){ float4 v=src[qq]; int c=qq*4;
            xv[c]=v.x; xv[c+1]=v.y; xv[c+2]=v.z; xv[c+3]=v.w; }
    } else {
        const float* Xin = (LAYER==1) ? g_y0 : g_y1;
        const float4* src = (const float4*)(Xin + (size_t)(m0p+t)*64);
#pragma unroll
        for (int qq=0; qq<16; qq++){ float4 v=src[qq]; int c=qq*4;
            xv[c]  = fmaxf(fmaf(v.x, g_scale[c],   g_shift[c]),   0.f);
            xv[c+1]= fmaxf(fmaf(v.y, g_scale[c+1], g_shift[c+1]), 0.f);
            xv[c+2]= fmaxf(fmaf(v.z, g_scale[c+2], g_shift[c+2]), 0.f);
            xv[c+3]= fmaxf(fmaf(v.w, g_scale[c+3], g_shift[c+3]), 0.f); }
    }
    // split to bf16 hi/lo, store swizzled A rows
    {
        u32 sw = (u32)((t&7)<<4);
#pragma unroll
        for (int c=0;c<32;c++){
            float x0=xv[2*c], x1=xv[2*c+1];
            __nv_bfloat16 h0=__float2bfloat16(x0), h1=__float2bfloat16(x1);
            float r0=x0-__bfloat162float(h0), r1=x1-__bfloat162float(h1);
            u32 off = ((u32)(c*4)) ^ sw;
            *(u32*)(sm+A_HI + t*128 + off) = (u32)(*(u16*)&h0) | ((u32)(*(u16*)&h1)<<16);
            *(u32*)(sm+A_LO + t*128 + off) = bfpack(r0,r1);
        }
    }
    __syncthreads();

    // ---- mainloop ----
    float acc[2][8][4];
#pragma unroll
    for (int mt=0; mt<2; mt++)
#pragma unroll
        for (int nt=0; nt<8; nt++)
#pragma unroll
            for (int j=0; j<4; j++) acc[mt][nt][j] = 0.f;

    const int qr = lane>>2, qc = lane&3;      // FIX: lane-based fragment coords
#pragma unroll
    for (int ks=0; ks<4; ks++) {
        u32 Ah[2][4], Al[2][4];
        u32 b0 = (u32)(ks*32 + qc*4);
#pragma unroll
        for (int mt=0; mt<2; mt++) {
            int r0 = w*32 + mt*16 + qr;
            u32 swz = (u32)((r0&7)<<4);
            Ah[mt][0] = *(u32*)(sm+A_HI + r0*128       + (b0^swz));
            Ah[mt][1] = *(u32*)(sm+A_HI + (r0+8)*128   + (b0^swz));
            Ah[mt][2] = *(u32*)(sm+A_HI + r0*128       + ((b0+16)^swz));
            Ah[mt][3] = *(u32*)(sm+A_HI + (r0+8)*128   + ((b0+16)^swz));
            Al[mt][0] = *(u32*)(sm+A_LO + r0*128       + (b0^swz));
            Al[mt][1] = *(u32*)(sm+A_LO + (r0+8)*128   + (b0^swz));
            Al[mt][2] = *(u32*)(sm+A_LO + r0*128       + ((b0+16)^swz));
            Al[mt][3] = *(u32*)(sm+A_LO + (r0+8)*128   + ((b0+16)^swz));
        }
#pragma unroll
        for (int nt=0; nt<8; nt++) {
            int nr = nt*8 + qr;
            u32 bs = (u32)((qr&7)<<4);
            u32 Bh0 = *(u32*)(sm+B_HI + nr*128 + (b0^bs));
            u32 Bh1 = *(u32*)(sm+B_HI + nr*128 + ((b0+16)^bs));
            u32 Bl0 = *(u32*)(sm+B_LO + nr*128 + (b0^bs));
            u32 Bl1 = *(u32*)(sm+B_LO + nr*128 + ((b0+16)^bs));
#pragma unroll
            for (int mt=0; mt<2; mt++) {
                MMA_BF16(acc[mt][nt], Ah[mt], Bh0, Bh1);
                MMA_BF16(acc[mt][nt], Ah[mt], Bl0, Bl1);
                MMA_BF16(acc[mt][nt], Al[mt], Bh0, Bh1);
            }
        }
    }
    __syncthreads();   // A/B smem free -> stats scratch

    // ---- epilogue: xyz add (L0), Y store (L0/L1), fused stats (+max L2) ----
    float* Ssm = (float*)sm;          // [4][64]
    float* Sqm = Ssm + 256;           // [4][64]
    const float* sdx = (const float*)(sm+DX);
    const float* Wx  = (const float*)(sm+WX);
    float* Y = (LAYER==0) ? g_y0 : g_y1;

#pragma unroll
    for (int nt=0; nt<8; nt++) {
        float y[2][4];
#pragma unroll
        for (int mt=0; mt<2; mt++)
#pragma unroll
            for (int j=0; j<4; j++) y[mt][j] = acc[mt][nt][j];
        if (LAYER == 0) {
#pragma unroll
            for (int mt=0; mt<2; mt++)
#pragma unroll
                for (int j=0; j<4; j++) {
                    int r = w*32 + mt*16 + qr + ((j>>1)<<3);
                    int ch = nt*8 + qc*2 + (j&1);
                    y[mt][j] = fmaf(sdx[r], Wx[ch],
                               fmaf(sdx[128+r], Wx[64+ch],
                               fmaf(sdx[256+r], Wx[128+ch], y[mt][j])));
                }
        }
        float s0 = y[0][0]+y[0][2]+y[1][0]+y[1][2];
        float s1 = y[0][1]+y[0][3]+y[1][1]+y[1][3];
        float q0 = y[0][0]*y[0][0]+y[0][2]*y[0][2]+y[1][0]*y[1][0]+y[1][2]*y[1][2];
        float q1 = y[0][1]*y[0][1]+y[0][3]*y[0][3]+y[1][1]*y[1][1]+y[1][3]*y[1][3];
        float mx0 = 0.f, mx1 = 0.f;
        if (LAYER == 2) {
            mx0 = fmaxf(fmaxf(y[0][0],y[0][2]), fmaxf(y[1][0],y[1][2]));
            mx1 = fmaxf(fmaxf(y[0][1],y[0][3]), fmaxf(y[1][1],y[1][3]));
        }
#pragma unroll
        for (int o=16; o>=4; o>>=1) {
            s0 += __shfl_down_sync(0xffffffffu, s0, o);
            s1 += __shfl_down_sync(0xffffffffu, s1, o);
            q0 += __shfl_down_sync(0xffffffffu, q0, o);
            q1 += __shfl_down_sync(0xffffffffu, q1, o);
            if (LAYER == 2) {
                mx0 = fmaxf(mx0, __shfl_down_sync(0xffffffffu, mx0, o));
                mx1 = fmaxf(mx1, __shfl_down_sync(0xffffffffu, mx1, o));
            }
        }
        if (lane < 4) {
            int ch = nt*8 + lane*2;
            Ssm[w*64 + ch] = s0;  Ssm[w*64 + ch + 1] = s1;
            Sqm[w*64 + ch] = q0;  Sqm[w*64 + ch + 1] = q1;
            if (LAYER == 2)
                *(float2*)(g_gmax + ((size_t)(m0p>>5) + w)*128 + n0 + ch) = make_float2(mx0, mx1);
        }
        if (LAYER != 2) {
#pragma unroll
            for (int mt=0; mt<2; mt++) {
                int r = m0p + w*32 + mt*16 + qr;
                int ch = nt*8 + qc*2;
                *(float2*)(Y + (size_t)r*64 + ch)     = make_float2(y[mt][0], y[mt][1]);
                *(float2*)(Y + (size_t)(r+8)*64 + ch) = make_float2(y[mt][2], y[mt][3]);
            }
        }
    }
    __syncthreads();
    if (t < 64) {
        float vs = Ssm[t] + Ssm[64+t] + Ssm[128+t] + Ssm[192+t];
        float vq = Sqm[t] + Sqm[64+t] + Sqm[128+t] + Sqm[192+t];
        size_t pi = (LAYER==2) ? ((size_t)blockIdx.x*128 + n0 + t)
                               : ((size_t)blockIdx.x*64 + t);
        g_parts[pi] = vs;
        g_partq[pi] = vq;
    }
}

// ============================================================================
// 4) finalize BN (unchanged)
// ============================================================================
template <int C>
__global__ __launch_bounds__(256)
void finalize_kernel(const float* __restrict__ g, const float* __restrict__ be)
{
    __shared__ double shs[256], shq[256];
    const int c = blockIdx.x, t = threadIdx.x;
    double s = 0.0, q = 0.0;
    for (int i = t; i < 4096; i += 256) {
        s += (double)g_parts[(size_t)i * C + c];
        q += (double)g_partq[(size_t)i * C + c];
    }
    shs[t] = s; shq[t] = q;
    __syncthreads();
    for (int o = 128; o; o >>= 1) {
        if (t < o) { shs[t] += shs[t+o]; shq[t] += shq[t+o]; }
        __syncthreads();
    }
    if (t == 0) {
        double mean = shs[0] / (double)Mm;
        double var  = shq[0] / (double)Mm - mean * mean;
        float sc = g[c] * (1.0f / sqrtf((float)var + 1e-5f));
        g_scale[c] = sc;
        g_shift[c] = fmaf(-(float)mean, sc, be[c]);
    }
}

// ============================================================================
// 5) output (unchanged)
// ============================================================================
__global__ __launch_bounds__(256)
void maxout_kernel(float* __restrict__ feats)
{
    int i = blockIdx.x * 256 + threadIdx.x;
    int c = i & 127;
    feats[i] = fmaxf(fmaf(g_gmax[i], g_scale[c], g_shift[c]), 0.f);
}

// ============================================================================
extern "C" void kernel_launch(void* const* d_in, const int* in_sizes, int n_in,
                              void* d_out, int out_size)
{
    const float* xyz = (const float*)d_in[0];
    const float* fea = (const float*)d_in[1];
    const float* W0  = (const float*)d_in[2];
    const float* g0  = (const float*)d_in[4];
    const float* be0 = (const float*)d_in[5];
    const float* W1  = (const float*)d_in[6];
    const float* g1  = (const float*)d_in[8];
    const float* be1 = (const float*)d_in[9];
    const float* W2  = (const float*)d_in[10];
    const float* g2  = (const float*)d_in[12];
    const float* be2 = (const float*)d_in[13];

    float* out   = (float*)d_out;
    float* samp  = out;
    float* feats = out + Bb * Ss * 3;

    const int fps_smem = Nn*16 + 2*16*8 + 16;
    const int knn_smem = Nn*16;
    const int mma_smem = 51456;

    cudaFuncSetAttribute(fps_kernel, cudaFuncAttributeMaxDynamicSharedMemorySize, fps_smem);
    cudaFuncSetAttribute(knn_kernel, cudaFuncAttributeMaxDynamicSharedMemorySize, knn_smem);
    cudaFuncSetAttribute(mma_kernel<0>, cudaFuncAttributeMaxDynamicSharedMemorySize, mma_smem);
    cudaFuncSetAttribute(mma_kernel<1>, cudaFuncAttributeMaxDynamicSharedMemorySize, mma_smem);
    cudaFuncSetAttribute(mma_kernel<2>, cudaFuncAttributeMaxDynamicSharedMemorySize, mma_smem);

    prep_kernel<<<16, 256>>>(W0, W1, W2);
    fps_kernel<<<Bb, 512, fps_smem>>>(xyz, samp);
    knn_kernel<<<dim3(Ss/16, Bb), 512, knn_smem>>>(xyz, samp);

    mma_kernel<0><<<Mm/128, 128, mma_smem>>>(fea, xyz, samp);
    finalize_kernel<64><<<64, 256>>>(g0, be0);

    mma_kernel<1><<<Mm/128, 128, mma_smem>>>(nullptr, nullptr, nullptr);
    finalize_kernel<64><<<64, 256>>>(g1, be1);

    mma_kernel<2><<<dim3(Mm/128, 2), 128, mma_smem>>>(nullptr, nullptr, nullptr);
    finalize_kernel<128><<<128, 256>>>(g2, be2);

    maxout_kernel<<<(Bb*Ss*128)/256, 256>>>(feats);
}

// round 12
// speedup vs baseline: 1.2261x; 1.0130x over previous
#include <cuda_runtime.h>
#include <cuda_bf16.h>
#include <math.h>

#define Bb 16
#define Nn 4096
#define Dd 64
#define Ss 1024
#define Kk 32
#define Mm (Bb*Ss*Kk)

typedef unsigned long long ull;
typedef unsigned int u32;
typedef unsigned short u16;

__device__ int    g_knn[Mm];
__device__ float  g_y0[Mm*64];
__device__ float  g_y1[Mm*64];
__device__ float  g_parts[4096*128];
__device__ float  g_partq[4096*128];
__device__ float  g_gmax[Bb*Ss*128];
__device__ float  g_scale[128];
__device__ float  g_shift[128];
__device__ __align__(16) u16 g_Bh[3][8192];  // bf16 hi W tiles [n][k], swizzled rows
__device__ __align__(16) u16 g_Bl[3][8192];  // bf16 lo
__device__ float  g_W0xyz[192];              // [3][64]

// ---- f32x2 helpers (fps) ----
__device__ __forceinline__ ull f2add(ull a, ull b){ ull d; asm("add.rn.f32x2 %0,%1,%2;":"=l"(d):"l"(a),"l"(b)); return d; }
__device__ __forceinline__ ull f2mul(ull a, ull b){ ull d; asm("mul.rn.f32x2 %0,%1,%2;":"=l"(d):"l"(a),"l"(b)); return d; }
__device__ __forceinline__ ull f2dup(float v){ ull d; asm("mov.b64 %0,{%1,%1};":"=l"(d):"f"(v)); return d; }
__device__ __forceinline__ ull f2pack(float l, float h){ ull d; asm("mov.b64 %0,{%1,%2};":"=l"(d):"f"(l),"f"(h)); return d; }
__device__ __forceinline__ void f2unpack(ull v, float& l, float& h){ asm("mov.b64 {%0,%1},%2;":"=f"(l),"=f"(h):"l"(v)); }
__device__ __forceinline__ unsigned mono(float f){ unsigned b=__float_as_uint(f); return b ^ (unsigned)(((int)b>>31)|0x80000000); }

__device__ __forceinline__ u32 bfpack(float a, float b){
    __nv_bfloat16 ha=__float2bfloat16(a), hb=__float2bfloat16(b);
    return (u32)(*(u16*)&ha) | ((u32)(*(u16*)&hb)<<16);
}
__device__ __forceinline__ u32 s2u(const void* p){
    u32 a; asm("{ .reg .u64 t; cvta.to.shared.u64 t, %1; cvt.u32.u64 %0, t; }":"=r"(a):"l"(p)); return a;
}

#define MMA_BF16(c, a, b0v, b1v) \
    asm volatile("mma.sync.aligned.m16n8k16.row.col.f32.bf16.bf16.f32 " \
        "{%0,%1,%2,%3},{%4,%5,%6,%7},{%8,%9},{%0,%1,%2,%3};" \
        : "+f"((c)[0]),"+f"((c)[1]),"+f"((c)[2]),"+f"((c)[3]) \
        : "r"((a)[0]),"r"((a)[1]),"r"((a)[2]),"r"((a)[3]), "r"(b0v),"r"(b1v))

#define LDSM_X4(r0,r1,r2,r3,addr) \
    asm volatile("ldmatrix.sync.aligned.m8n8.x4.shared.b16 {%0,%1,%2,%3}, [%4];" \
        : "=r"(r0),"=r"(r1),"=r"(r2),"=r"(r3) : "r"(addr))

// ============================================================================
// 0) prep: split W into bf16 hi/lo, rows [n][k] 128B with XOR swizzle applied
// ============================================================================
__device__ __forceinline__ void wsplit(float x, u16* H, u16* L, int o, int k){
    __nv_bfloat16 h = __float2bfloat16(x);
    float r = x - __bfloat162float(h);
    __nv_bfloat16 l = __float2bfloat16(r);
    u32 off = (u32)(o*128) + (((u32)(k*2)) ^ (u32)((o&7)<<4));
    H[off>>1] = *(u16*)&h;  L[off>>1] = *(u16*)&l;
}
__global__ void prep_kernel(const float* __restrict__ W0, const float* __restrict__ W1,
                            const float* __restrict__ W2){
    int t = blockIdx.x*256+threadIdx.x, st = gridDim.x*256;
    for (int i=t;i<4096;i+=st){ int o=i>>6,k=i&63; wsplit(W0[o*67+3+k], g_Bh[0], g_Bl[0], o,k); }
    for (int i=t;i<4096;i+=st){ int o=i>>6,k=i&63; wsplit(W1[o*64+k],   g_Bh[1], g_Bl[1], o,k); }
    for (int i=t;i<8192;i+=st){ int o=i>>6,k=i&63; wsplit(W2[o*64+k],   g_Bh[2], g_Bl[2], o,k); }
    for (int i=t;i<192;i+=st){ int j=i>>6,o=i&63; g_W0xyz[j*64+o] = W0[o*67+j]; }
}

// ============================================================================
// 1) FPS (unchanged — bit-exact, single barrier/iter)
// ============================================================================
__global__ __launch_bounds__(512, 1)
void fps_kernel(const float* __restrict__ xyz, float* __restrict__ out_xyz)
{
    extern __shared__ float4 sp[];
    ull* s_key = (ull*)(sp + Nn);
    const int b = blockIdx.x, tid = threadIdx.x;
    const int lane = tid & 31, warp = tid >> 5;
    const float* base = xyz + (size_t)b * Nn * 3;

    ull px2[4], py2[4], pz2[4];
    float dist[8];
#pragma unroll
    for (int j = 0; j < 4; j++) {
        int plo = tid + (2*j)*512, phi = tid + (2*j+1)*512;
        float Xl = base[plo*3+0], Yl = base[plo*3+1], Zl = base[plo*3+2];
        float Xh = base[phi*3+0], Yh = base[phi*3+1], Zh = base[phi*3+2];
        sp[plo] = make_float4(Xl, Yl, Zl, 0.f);
        sp[phi] = make_float4(Xh, Yh, Zh, 0.f);
        px2[j] = f2pack(Xl, Xh); py2[j] = f2pack(Yl, Yh); pz2[j] = f2pack(Zl, Zh);
        dist[2*j] = 1e10f; dist[2*j+1] = 1e10f;
    }
    __syncthreads();

    int far = 0;
    float* ob = out_xyz + (size_t)b * Ss * 3;
    for (int it = 0; it < Ss; ++it) {
        float4 c = sp[far];
        if (tid == 0) { ob[it*3+0]=c.x; ob[it*3+1]=c.y; ob[it*3+2]=c.z; }
        ull ncx = f2dup(-c.x), ncy = f2dup(-c.y), ncz = f2dup(-c.z);
        unsigned u[8];
#pragma unroll
        for (int j = 0; j < 4; j++) {
            ull dx = f2add(px2[j], ncx), dy = f2add(py2[j], ncy), dz = f2add(pz2[j], ncz);
            ull s = f2add(f2add(f2mul(dx,dx), f2mul(dy,dy)), f2mul(dz,dz));
            float lo, hi; f2unpack(s, lo, hi);
            float dl = fminf(dist[2*j], lo), dh = fminf(dist[2*j+1], hi);
            dist[2*j] = dl; dist[2*j+1] = dh;
            u[2*j] = __float_as_uint(dl); u[2*j+1] = __float_as_uint(dh);
        }
        unsigned v[4], jx[4];
#pragma unroll
        for (int j = 0; j < 4; j++) {
            bool g = u[2*j+1] > u[2*j];
            v[j] = g ? u[2*j+1] : u[2*j];
            jx[j] = 2*j + (g ? 1u : 0u);
        }
        bool ga = v[1] > v[0];
        unsigned va = ga ? v[1] : v[0], ja = ga ? jx[1] : jx[0];
        bool gb = v[3] > v[2];
        unsigned vb2 = gb ? v[3] : v[2], jb = gb ? jx[3] : jx[2];
        bool gc = vb2 > va;
        unsigned bb = gc ? vb2 : va, jj = gc ? jb : ja;
        int bi = tid + (int)jj * 512;

        unsigned mv = __reduce_max_sync(0xffffffffu, bb);
        int ci = (bb == mv) ? bi : 0x7fffffff;
        int mi = __reduce_min_sync(0xffffffffu, ci);
        if (lane == 0)
            s_key[(it&1)*16 + warp] = ((ull)mv << 32) | (unsigned)(0x7fffffff - mi);
        __syncthreads();
        ull k = s_key[(it&1)*16 + (lane & 15)];
        unsigned hv = (unsigned)(k >> 32), lv = (unsigned)k;
        unsigned mh = __reduce_max_sync(0xffffffffu, hv);
        unsigned ml = __reduce_max_sync(0xffffffffu, (hv == mh) ? lv : 0u);
        far = 0x7fffffff - (int)ml;
    }
}

// ============================================================================
// 2) KNN (unchanged): warp per query, single pass
// ============================================================================
__global__ __launch_bounds__(512, 1)
void knn_kernel(const float* __restrict__ xyz, const float* __restrict__ samp)
{
    extern __shared__ float4 sq[];
    const int b = blockIdx.y, t = threadIdx.x;
    const int lane = t & 31, w = t >> 5;
    const float* base = xyz + (size_t)b * Nn * 3;
    for (int j = t; j < Nn; j += 512) {
        float x = base[j*3], y = base[j*3+1], z = base[j*3+2];
        sq[j] = make_float4(x, y, z, fmaf(x,x, fmaf(y,y, z*z)));
    }
    __syncthreads();

    const int q = b * Ss + blockIdx.x * 16 + w;
    float qx = samp[q*3], qy = samp[q*3+1], qz = samp[q*3+2];
    float ax = -2.0f*qx, ay = -2.0f*qy, az = -2.0f*qz;

    float4 p0 = sq[lane];
    unsigned held = mono(fmaf(az, p0.z, fmaf(ay, p0.y, fmaf(ax, p0.x, p0.w))));
    int held_idx = lane;
    unsigned thr = __reduce_max_sync(0xffffffffu, held);

#pragma unroll 1
    for (int step = 1; step < Nn/32; step++) {
        float4 p = sq[step*32 + lane];
        unsigned u = mono(fmaf(az, p.z, fmaf(ay, p.y, fmaf(ax, p.x, p.w))));
        unsigned m = __ballot_sync(0xffffffffu, u < thr);
        while (m) {
            int src = __ffs(m) - 1;
            unsigned uc = __shfl_sync(0xffffffffu, u, src);
            if (uc < thr) {
                unsigned vb = __ballot_sync(0xffffffffu, held == thr);
                int victim = __ffs(vb) - 1;
                if (lane == victim) { held = uc; held_idx = step*32 + src; }
                thr = __reduce_max_sync(0xffffffffu, held);
            }
            m &= m - 1;
            m &= __ballot_sync(0xffffffffu, u < thr);
        }
    }
    g_knn[(size_t)q * Kk + lane] = held_idx;
}

// ============================================================================
// 3) MLP layer via mma.sync bf16-split + ldmatrix fragment loads.
// ============================================================================
template <int LAYER>
__global__ __launch_bounds__(128)
void mma_kernel(const float* __restrict__ fea, const float* __restrict__ xyz,
                const float* __restrict__ samp)
{
    extern __shared__ __align__(16) char sm[];
    const int A_HI=0, A_LO=16384, B_HI=32768, B_LO=40960, DX=49152, WX=50688;
    const int t = threadIdx.x, lane = t&31, w = t>>5;
    const int m0p = blockIdx.x*128;
    const int n0  = (LAYER==2) ? blockIdx.y*64 : 0;

    // ---- B tiles -> smem (plain copy; swizzle already applied) ----
    {
        const uint4* BH = (const uint4*)(g_Bh[LAYER]) + n0*8;
        const uint4* BL = (const uint4*)(g_Bl[LAYER]) + n0*8;
        uint4* dh = (uint4*)(sm+B_HI); uint4* dl = (uint4*)(sm+B_LO);
#pragma unroll
        for (int i = 0; i < 4; i++) { dh[t+128*i] = BH[t+128*i]; dl[t+128*i] = BL[t+128*i]; }
    }

    // ---- X row load (+BN-ReLU for layers 1/2) ----
    float xv[64];
    if (LAYER == 0) {
        int m = m0p + t, g = m>>5, idx = g_knn[m];
        int row = (g>>10)*Nn + idx;
        float dx = xyz[row*3+0]-samp[g*3+0];
        float dy = xyz[row*3+1]-samp[g*3+1];
        float dz = xyz[row*3+2]-samp[g*3+2];
        ((float*)(sm+DX))[t] = dx; ((float*)(sm+DX))[128+t] = dy; ((float*)(sm+DX))[256+t] = dz;
        for (int i=t;i<192;i+=128) ((float*)(sm+WX))[i] = g_W0xyz[i];
        const float4* src = (const float4*)(fea + (size_t)row*Dd);
#pragma unroll
        for (int qq=0; qq<16; qq++){ float4 v=src[qq]; int c=qq*4;
            xv[c]=v.x; xv[c+1]=v.y; xv[c+2]=v.z; xv[c+3]=v.w; }
    } else {
        const float* Xin = (LAYER==1) ? g_y0 : g_y1;
        const float4* src = (const float4*)(Xin + (size_t)(m0p+t)*64);
#pragma unroll
        for (int qq=0; qq<16; qq++){ float4 v=src[qq]; int c=qq*4;
            xv[c]  = fmaxf(fmaf(v.x, g_scale[c],   g_shift[c]),   0.f);
            xv[c+1]= fmaxf(fmaf(v.y, g_scale[c+1], g_shift[c+1]), 0.f);
            xv[c+2]= fmaxf(fmaf(v.z, g_scale[c+2], g_shift[c+2]), 0.f);
            xv[c+3]= fmaxf(fmaf(v.w, g_scale[c+3], g_shift[c+3]), 0.f); }
    }
    {
        u32 sw = (u32)((t&7)<<4);
#pragma unroll
        for (int c=0;c<32;c++){
            float x0=xv[2*c], x1=xv[2*c+1];
            __nv_bfloat16 h0=__float2bfloat16(x0), h1=__float2bfloat16(x1);
            float r0=x0-__bfloat162float(h0), r1=x1-__bfloat162float(h1);
            u32 off = ((u32)(c*4)) ^ sw;
            *(u32*)(sm+A_HI + t*128 + off) = (u32)(*(u16*)&h0) | ((u32)(*(u16*)&h1)<<16);
            *(u32*)(sm+A_LO + t*128 + off) = bfpack(r0,r1);
        }
    }
    __syncthreads();

    // ---- mainloop (ldmatrix fragment loads) ----
    float acc[2][8][4];
#pragma unroll
    for (int mt=0; mt<2; mt++)
#pragma unroll
        for (int nt=0; nt<8; nt++)
#pragma unroll
            for (int j=0; j<4; j++) acc[mt][nt][j] = 0.f;

    const u32 sbase = s2u(sm);
    const int qr = lane>>2, qc = lane&3;
    // ldmatrix lane-address components (constant across ks):
    const u32 aRowSel = (u32)(((lane>>3)&1)*8 + (lane&7));   // row within 16
    const u32 aKSel   = (u32)((lane>>4)*16);                 // +16B for a2/a3
    const u32 bNSel   = (u32)((lane>>4)*8 + (lane&7));       // n row within 16
    const u32 bKSel   = (u32)(((lane>>3)&1)*16);             // +16B for b1

#pragma unroll
    for (int ks=0; ks<4; ks++) {
        const u32 kb = (u32)(ks*32);
        u32 Ah[2][4], Al[2][4];
#pragma unroll
        for (int mt=0; mt<2; mt++) {
            u32 row = (u32)(w*32 + mt*16) + aRowSel;
            u32 col = (kb + aKSel) ^ ((row&7)<<4);
            u32 adr = sbase + A_HI + row*128 + col;
            LDSM_X4(Ah[mt][0], Ah[mt][1], Ah[mt][2], Ah[mt][3], adr);
            LDSM_X4(Al[mt][0], Al[mt][1], Al[mt][2], Al[mt][3], adr + (u32)(A_LO - A_HI));
        }
#pragma unroll
        for (int ntp=0; ntp<4; ntp++) {
            u32 nrow = (u32)(ntp*16) + bNSel;
            u32 col  = (kb + bKSel) ^ ((nrow&7)<<4);
            u32 badr = sbase + B_HI + nrow*128 + col;
            u32 bh0, bh1, bh2, bh3, bl0, bl1, bl2, bl3;
            LDSM_X4(bh0, bh1, bh2, bh3, badr);
            LDSM_X4(bl0, bl1, bl2, bl3, badr + (u32)(B_LO - B_HI));
#pragma unroll
            for (int mt=0; mt<2; mt++) {
                MMA_BF16(acc[mt][2*ntp],   Ah[mt], bh0, bh1);
                MMA_BF16(acc[mt][2*ntp],   Ah[mt], bl0, bl1);
                MMA_BF16(acc[mt][2*ntp],   Al[mt], bh0, bh1);
                MMA_BF16(acc[mt][2*ntp+1], Ah[mt], bh2, bh3);
                MMA_BF16(acc[mt][2*ntp+1], Ah[mt], bl2, bl3);
                MMA_BF16(acc[mt][2*ntp+1], Al[mt], bh2, bh3);
            }
        }
    }
    __syncthreads();   // A/B smem free -> stats scratch

    // ---- epilogue: xyz add (L0), Y store (L0/L1), fused stats (+max L2) ----
    float* Ssm = (float*)sm;          // [4][64]
    float* Sqm = Ssm + 256;           // [4][64]
    const float* sdx = (const float*)(sm+DX);
    const float* Wx  = (const float*)(sm+WX);
    float* Y = (LAYER==0) ? g_y0 : g_y1;

#pragma unroll
    for (int nt=0; nt<8; nt++) {
        float y[2][4];
#pragma unroll
        for (int mt=0; mt<2; mt++)
#pragma unroll
            for (int j=0; j<4; j++) y[mt][j] = acc[mt][nt][j];
        if (LAYER == 0) {
#pragma unroll
            for (int mt=0; mt<2; mt++)
#pragma unroll
                for (int j=0; j<4; j++) {
                    int r = w*32 + mt*16 + qr + ((j>>1)<<3);
                    int ch = nt*8 + qc*2 + (j&1);
                    y[mt][j] = fmaf(sdx[r], Wx[ch],
                               fmaf(sdx[128+r], Wx[64+ch],
                               fmaf(sdx[256+r], Wx[128+ch], y[mt][j])));
                }
        }
        float s0 = y[0][0]+y[0][2]+y[1][0]+y[1][2];
        float s1 = y[0][1]+y[0][3]+y[1][1]+y[1][3];
        float q0 = y[0][0]*y[0][0]+y[0][2]*y[0][2]+y[1][0]*y[1][0]+y[1][2]*y[1][2];
        float q1 = y[0][1]*y[0][1]+y[0][3]*y[0][3]+y[1][1]*y[1][1]+y[1][3]*y[1][3];
        float mx0 = 0.f, mx1 = 0.f;
        if (LAYER == 2) {
            mx0 = fmaxf(fmaxf(y[0][0],y[0][2]), fmaxf(y[1][0],y[1][2]));
            mx1 = fmaxf(fmaxf(y[0][1],y[0][3]), fmaxf(y[1][1],y[1][3]));
        }
#pragma unroll
        for (int o=16; o>=4; o>>=1) {
            s0 += __shfl_down_sync(0xffffffffu, s0, o);
            s1 += __shfl_down_sync(0xffffffffu, s1, o);
            q0 += __shfl_down_sync(0xffffffffu, q0, o);
            q1 += __shfl_down_sync(0xffffffffu, q1, o);
            if (LAYER == 2) {
                mx0 = fmaxf(mx0, __shfl_down_sync(0xffffffffu, mx0, o));
                mx1 = fmaxf(mx1, __shfl_down_sync(0xffffffffu, mx1, o));
            }
        }
        if (lane < 4) {
            int ch = nt*8 + lane*2;
            Ssm[w*64 + ch] = s0;  Ssm[w*64 + ch + 1] = s1;
            Sqm[w*64 + ch] = q0;  Sqm[w*64 + ch + 1] = q1;
            if (LAYER == 2)
                *(float2*)(g_gmax + ((size_t)(m0p>>5) + w)*128 + n0 + ch) = make_float2(mx0, mx1);
        }
        if (LAYER != 2) {
#pragma unroll
            for (int mt=0; mt<2; mt++) {
                int r = m0p + w*32 + mt*16 + qr;
                int ch = nt*8 + qc*2;
                *(float2*)(Y + (size_t)r*64 + ch)     = make_float2(y[mt][0], y[mt][1]);
                *(float2*)(Y + (size_t)(r+8)*64 + ch) = make_float2(y[mt][2], y[mt][3]);
            }
        }
    }
    __syncthreads();
    if (t < 64) {
        float vs = Ssm[t] + Ssm[64+t] + Ssm[128+t] + Ssm[192+t];
        float vq = Sqm[t] + Sqm[64+t] + Sqm[128+t] + Sqm[192+t];
        size_t pi = (LAYER==2) ? ((size_t)blockIdx.x*128 + n0 + t)
                               : ((size_t)blockIdx.x*64 + t);
        g_parts[pi] = vs;
        g_partq[pi] = vq;
    }
}

// ============================================================================
// 4) finalize BN (unchanged)
// ============================================================================
template <int C>
__global__ __launch_bounds__(256)
void finalize_kernel(const float* __restrict__ g, const float* __restrict__ be)
{
    __shared__ double shs[256], shq[256];
    const int c = blockIdx.x, t = threadIdx.x;
    double s = 0.0, q = 0.0;
    for (int i = t; i < 4096; i += 256) {
        s += (double)g_parts[(size_t)i * C + c];
        q += (double)g_partq[(size_t)i * C + c];
    }
    shs[t] = s; shq[t] = q;
    __syncthreads();
    for (int o = 128; o; o >>= 1) {
        if (t < o) { shs[t] += shs[t+o]; shq[t] += shq[t+o]; }
        __syncthreads();
    }
    if (t == 0) {
        double mean = shs[0] / (double)Mm;
        double var  = shq[0] / (double)Mm - mean * mean;
        float sc = g[c] * (1.0f / sqrtf((float)var + 1e-5f));
        g_scale[c] = sc;
        g_shift[c] = fmaf(-(float)mean, sc, be[c]);
    }
}

// ============================================================================
// 5) output (unchanged)
// ============================================================================
__global__ __launch_bounds__(256)
void maxout_kernel(float* __restrict__ feats)
{
    int i = blockIdx.x * 256 + threadIdx.x;
    int c = i & 127;
    feats[i] = fmaxf(fmaf(g_gmax[i], g_scale[c], g_shift[c]), 0.f);
}

// ============================================================================
extern "C" void kernel_launch(void* const* d_in, const int* in_sizes, int n_in,
                              void* d_out, int out_size)
{
    const float* xyz = (const float*)d_in[0];
    const float* fea = (const float*)d_in[1];
    const float* W0  = (const float*)d_in[2];
    const float* g0  = (const float*)d_in[4];
    const float* be0 = (const float*)d_in[5];
    const float* W1  = (const float*)d_in[6];
    const float* g1  = (const float*)d_in[8];
    const float* be1 = (const float*)d_in[9];
    const float* W2  = (const float*)d_in[10];
    const float* g2  = (const float*)d_in[12];
    const float* be2 = (const float*)d_in[13];

    float* out   = (float*)d_out;
    float* samp  = out;
    float* feats = out + Bb * Ss * 3;

    const int fps_smem = Nn*16 + 2*16*8 + 16;
    const int knn_smem = Nn*16;
    const int mma_smem = 51456;

    cudaFuncSetAttribute(fps_kernel, cudaFuncAttributeMaxDynamicSharedMemorySize, fps_smem);
    cudaFuncSetAttribute(knn_kernel, cudaFuncAttributeMaxDynamicSharedMemorySize, knn_smem);
    cudaFuncSetAttribute(mma_kernel<0>, cudaFuncAttributeMaxDynamicSharedMemorySize, mma_smem);
    cudaFuncSetAttribute(mma_kernel<1>, cudaFuncAttributeMaxDynamicSharedMemorySize, mma_smem);
    cudaFuncSetAttribute(mma_kernel<2>, cudaFuncAttributeMaxDynamicSharedMemorySize, mma_smem);

    prep_kernel<<<16, 256>>>(W0, W1, W2);
    fps_kernel<<<Bb, 512, fps_smem>>>(xyz, samp);
    knn_kernel<<<dim3(Ss/16, Bb), 512, knn_smem>>>(xyz, samp);

    mma_kernel<0><<<Mm/128, 128, mma_smem>>>(fea, xyz, samp);
    finalize_kernel<64><<<64, 256>>>(g0, be0);

    mma_kernel<1><<<Mm/128, 128, mma_smem>>>(nullptr, nullptr, nullptr);
    finalize_kernel<64><<<64, 256>>>(g1, be1);

    mma_kernel<2><<<dim3(Mm/128, 2), 128, mma_smem>>>(nullptr, nullptr, nullptr);
    finalize_kernel<128><<<128, 256>>>(g2, be2);

    maxout_kernel<<<(Bb*Ss*128)/256, 256>>>(feats);
}

// round 13
// speedup vs baseline: 1.3938x; 1.1368x over previous
#include <cuda_runtime.h>
#include <cuda_bf16.h>
#include <math.h>

#define Bb 16
#define Nn 4096
#define Dd 64
#define Ss 1024
#define Kk 32
#define Mm (Bb*Ss*Kk)

typedef unsigned long long ull;
typedef unsigned int u32;
typedef unsigned short u16;

__device__ int    g_knn[Mm];
__device__ float  g_y0[Mm*64];
__device__ float  g_y1[Mm*64];
__device__ float  g_parts[4096*128];
__device__ float  g_partq[4096*128];
__device__ float  g_gmax[Bb*Ss*128];
__device__ float  g_scale[128];
__device__ float  g_shift[128];
__device__ __align__(16) u16 g_Bh[3][8192];  // bf16 hi W tiles [n][k], swizzled rows
__device__ __align__(16) u16 g_Bl[3][8192];  // bf16 lo
__device__ float  g_W0xyz[192];              // [3][64]

// ---- f32x2 helpers (fps) ----
__device__ __forceinline__ ull f2add(ull a, ull b){ ull d; asm("add.rn.f32x2 %0,%1,%2;":"=l"(d):"l"(a),"l"(b)); return d; }
__device__ __forceinline__ ull f2mul(ull a, ull b){ ull d; asm("mul.rn.f32x2 %0,%1,%2;":"=l"(d):"l"(a),"l"(b)); return d; }
__device__ __forceinline__ ull f2dup(float v){ ull d; asm("mov.b64 %0,{%1,%1};":"=l"(d):"f"(v)); return d; }
__device__ __forceinline__ ull f2pack(float l, float h){ ull d; asm("mov.b64 %0,{%1,%2};":"=l"(d):"f"(l),"f"(h)); return d; }
__device__ __forceinline__ void f2unpack(ull v, float& l, float& h){ asm("mov.b64 {%0,%1},%2;":"=f"(l),"=f"(h):"l"(v)); }
__device__ __forceinline__ unsigned mono(float f){ unsigned b=__float_as_uint(f); return b ^ (unsigned)(((int)b>>31)|0x80000000); }

__device__ __forceinline__ u32 bfpack(float a, float b){
    __nv_bfloat16 ha=__float2bfloat16(a), hb=__float2bfloat16(b);
    return (u32)(*(u16*)&ha) | ((u32)(*(u16*)&hb)<<16);
}
__device__ __forceinline__ u32 s2u(const void* p){
    u32 a; asm("{ .reg .u64 t; cvta.to.shared.u64 t, %1; cvt.u32.u64 %0, t; }":"=r"(a):"l"(p)); return a;
}

#define MMA_BF16(c, a, b0v, b1v) \
    asm volatile("mma.sync.aligned.m16n8k16.row.col.f32.bf16.bf16.f32 " \
        "{%0,%1,%2,%3},{%4,%5,%6,%7},{%8,%9},{%0,%1,%2,%3};" \
        : "+f"((c)[0]),"+f"((c)[1]),"+f"((c)[2]),"+f"((c)[3]) \
        : "r"((a)[0]),"r"((a)[1]),"r"((a)[2]),"r"((a)[3]), "r"(b0v),"r"(b1v))

#define LDSM_X4(r0,r1,r2,r3,addr) \
    asm volatile("ldmatrix.sync.aligned.m8n8.x4.shared.b16 {%0,%1,%2,%3}, [%4];" \
        : "=r"(r0),"=r"(r1),"=r"(r2),"=r"(r3) : "r"(addr))

// ============================================================================
// 0) prep: split W into bf16 hi/lo, rows [n][k] 128B with XOR swizzle applied
// ============================================================================
__device__ __forceinline__ void wsplit(float x, u16* H, u16* L, int o, int k){
    __nv_bfloat16 h = __float2bfloat16(x);
    float r = x - __bfloat162float(h);
    __nv_bfloat16 l = __float2bfloat16(r);
    u32 off = (u32)(o*128) + (((u32)(k*2)) ^ (u32)((o&7)<<4));
    H[off>>1] = *(u16*)&h;  L[off>>1] = *(u16*)&l;
}
__global__ void prep_kernel(const float* __restrict__ W0, const float* __restrict__ W1,
                            const float* __restrict__ W2){
    int t = blockIdx.x*256+threadIdx.x, st = gridDim.x*256;
    for (int i=t;i<4096;i+=st){ int o=i>>6,k=i&63; wsplit(W0[o*67+3+k], g_Bh[0], g_Bl[0], o,k); }
    for (int i=t;i<4096;i+=st){ int o=i>>6,k=i&63; wsplit(W1[o*64+k],   g_Bh[1], g_Bl[1], o,k); }
    for (int i=t;i<8192;i+=st){ int o=i>>6,k=i&63; wsplit(W2[o*64+k],   g_Bh[2], g_Bl[2], o,k); }
    for (int i=t;i<192;i+=st){ int j=i>>6,o=i&63; g_W0xyz[j*64+o] = W0[o*67+j]; }
}

// ============================================================================
// 1) FPS (unchanged — bit-exact, single barrier/iter)
// ============================================================================
__global__ __launch_bounds__(512, 1)
void fps_kernel(const float* __restrict__ xyz, float* __restrict__ out_xyz)
{
    extern __shared__ float4 sp[];
    ull* s_key = (ull*)(sp + Nn);
    const int b = blockIdx.x, tid = threadIdx.x;
    const int lane = tid & 31, warp = tid >> 5;
    const float* base = xyz + (size_t)b * Nn * 3;

    ull px2[4], py2[4], pz2[4];
    float dist[8];
#pragma unroll
    for (int j = 0; j < 4; j++) {
        int plo = tid + (2*j)*512, phi = tid + (2*j+1)*512;
        float Xl = base[plo*3+0], Yl = base[plo*3+1], Zl = base[plo*3+2];
        float Xh = base[phi*3+0], Yh = base[phi*3+1], Zh = base[phi*3+2];
        sp[plo] = make_float4(Xl, Yl, Zl, 0.f);
        sp[phi] = make_float4(Xh, Yh, Zh, 0.f);
        px2[j] = f2pack(Xl, Xh); py2[j] = f2pack(Yl, Yh); pz2[j] = f2pack(Zl, Zh);
        dist[2*j] = 1e10f; dist[2*j+1] = 1e10f;
    }
    __syncthreads();

    int far = 0;
    float* ob = out_xyz + (size_t)b * Ss * 3;
    for (int it = 0; it < Ss; ++it) {
        float4 c = sp[far];
        if (tid == 0) { ob[it*3+0]=c.x; ob[it*3+1]=c.y; ob[it*3+2]=c.z; }
        ull ncx = f2dup(-c.x), ncy = f2dup(-c.y), ncz = f2dup(-c.z);
        unsigned u[8];
#pragma unroll
        for (int j = 0; j < 4; j++) {
            ull dx = f2add(px2[j], ncx), dy = f2add(py2[j], ncy), dz = f2add(pz2[j], ncz);
            ull s = f2add(f2add(f2mul(dx,dx), f2mul(dy,dy)), f2mul(dz,dz));
            float lo, hi; f2unpack(s, lo, hi);
            float dl = fminf(dist[2*j], lo), dh = fminf(dist[2*j+1], hi);
            dist[2*j] = dl; dist[2*j+1] = dh;
            u[2*j] = __float_as_uint(dl); u[2*j+1] = __float_as_uint(dh);
        }
        unsigned v[4], jx[4];
#pragma unroll
        for (int j = 0; j < 4; j++) {
            bool g = u[2*j+1] > u[2*j];
            v[j] = g ? u[2*j+1] : u[2*j];
            jx[j] = 2*j + (g ? 1u : 0u);
        }
        bool ga = v[1] > v[0];
        unsigned va = ga ? v[1] : v[0], ja = ga ? jx[1] : jx[0];
        bool gb = v[3] > v[2];
        unsigned vb2 = gb ? v[3] : v[2], jb = gb ? jx[3] : jx[2];
        bool gc = vb2 > va;
        unsigned bb = gc ? vb2 : va, jj = gc ? jb : ja;
        int bi = tid + (int)jj * 512;

        unsigned mv = __reduce_max_sync(0xffffffffu, bb);
        int ci = (bb == mv) ? bi : 0x7fffffff;
        int mi = __reduce_min_sync(0xffffffffu, ci);
        if (lane == 0)
            s_key[(it&1)*16 + warp] = ((ull)mv << 32) | (unsigned)(0x7fffffff - mi);
        __syncthreads();
        ull k = s_key[(it&1)*16 + (lane & 15)];
        unsigned hv = (unsigned)(k >> 32), lv = (unsigned)k;
        unsigned mh = __reduce_max_sync(0xffffffffu, hv);
        unsigned ml = __reduce_max_sync(0xffffffffu, (hv == mh) ? lv : 0u);
        far = 0x7fffffff - (int)ml;
    }
}

// ============================================================================
// 2) KNN (unchanged): warp per query, single pass
// ============================================================================
__global__ __launch_bounds__(512, 1)
void knn_kernel(const float* __restrict__ xyz, const float* __restrict__ samp)
{
    extern __shared__ float4 sq[];
    const int b = blockIdx.y, t = threadIdx.x;
    const int lane = t & 31, w = t >> 5;
    const float* base = xyz + (size_t)b * Nn * 3;
    for (int j = t; j < Nn; j += 512) {
        float x = base[j*3], y = base[j*3+1], z = base[j*3+2];
        sq[j] = make_float4(x, y, z, fmaf(x,x, fmaf(y,y, z*z)));
    }
    __syncthreads();

    const int q = b * Ss + blockIdx.x * 16 + w;
    float qx = samp[q*3], qy = samp[q*3+1], qz = samp[q*3+2];
    float ax = -2.0f*qx, ay = -2.0f*qy, az = -2.0f*qz;

    float4 p0 = sq[lane];
    unsigned held = mono(fmaf(az, p0.z, fmaf(ay, p0.y, fmaf(ax, p0.x, p0.w))));
    int held_idx = lane;
    unsigned thr = __reduce_max_sync(0xffffffffu, held);

#pragma unroll 1
    for (int step = 1; step < Nn/32; step++) {
        float4 p = sq[step*32 + lane];
        unsigned u = mono(fmaf(az, p.z, fmaf(ay, p.y, fmaf(ax, p.x, p.w))));
        unsigned m = __ballot_sync(0xffffffffu, u < thr);
        while (m) {
            int src = __ffs(m) - 1;
            unsigned uc = __shfl_sync(0xffffffffu, u, src);
            if (uc < thr) {
                unsigned vb = __ballot_sync(0xffffffffu, held == thr);
                int victim = __ffs(vb) - 1;
                if (lane == victim) { held = uc; held_idx = step*32 + src; }
                thr = __reduce_max_sync(0xffffffffu, held);
            }
            m &= m - 1;
            m &= __ballot_sync(0xffffffffu, u < thr);
        }
    }
    g_knn[(size_t)q * Kk + lane] = held_idx;
}

// ============================================================================
// 3) MLP layer via mma.sync bf16-split + ldmatrix; X loads warp-cooperative
//    (16 lanes/row, 2 rows per warp instruction -> coalesced gather).
// ============================================================================
template <int LAYER>
__global__ __launch_bounds__(128)
void mma_kernel(const float* __restrict__ fea, const float* __restrict__ xyz,
                const float* __restrict__ samp)
{
    extern __shared__ __align__(16) char sm[];
    const int A_HI=0, A_LO=16384, B_HI=32768, B_LO=40960, DX=49152, WX=50688, IDX=51456;
    const int t = threadIdx.x, lane = t&31, w = t>>5;
    const int m0p = blockIdx.x*128;
    const int n0  = (LAYER==2) ? blockIdx.y*64 : 0;

    // ---- B tiles -> smem (plain copy; swizzle already applied) ----
    {
        const uint4* BH = (const uint4*)(g_Bh[LAYER]) + n0*8;
        const uint4* BL = (const uint4*)(g_Bl[LAYER]) + n0*8;
        uint4* dh = (uint4*)(sm+B_HI); uint4* dl = (uint4*)(sm+B_LO);
#pragma unroll
        for (int i = 0; i < 4; i++) { dh[t+128*i] = BH[t+128*i]; dl[t+128*i] = BL[t+128*i]; }
    }

    // ---- X tile: warp-cooperative, coalesced ----
    const int rloc0 = w*32 + (lane>>4);   // this lane's first row (2 rows/iter)
    const int c4 = lane & 15;             // channel quad 4*c4..4*c4+3
    const int cc = c4*4;
    if (LAYER == 0) {
        int m = m0p + t, g = m>>5, idx = g_knn[m];
        int row = (g>>10)*Nn + idx;
        ((int*)(sm+IDX))[t] = row;
        ((float*)(sm+DX))[t]     = xyz[row*3+0]-samp[g*3+0];
        ((float*)(sm+DX))[128+t] = xyz[row*3+1]-samp[g*3+1];
        ((float*)(sm+DX))[256+t] = xyz[row*3+2]-samp[g*3+2];
        for (int i=t;i<192;i+=128) ((float*)(sm+WX))[i] = g_W0xyz[i];
        __syncthreads();
#pragma unroll 4
        for (int it2 = 0; it2 < 16; it2++) {
            int rr = rloc0 + it2*2;
            int gr = ((const int*)(sm+IDX))[rr];
            float4 v = *(const float4*)(fea + (size_t)gr*Dd + cc);
            u32 sw = (u32)((rr&7)<<4);
            __nv_bfloat16 h0=__float2bfloat16(v.x), h1=__float2bfloat16(v.y);
            __nv_bfloat16 h2=__float2bfloat16(v.z), h3=__float2bfloat16(v.w);
            u32 o0 = ((u32)(cc*2)) ^ sw;
            *(u32*)(sm+A_HI + rr*128 + o0)   = (u32)(*(u16*)&h0) | ((u32)(*(u16*)&h1)<<16);
            *(u32*)(sm+A_HI + rr*128 + o0+4) = (u32)(*(u16*)&h2) | ((u32)(*(u16*)&h3)<<16);
            *(u32*)(sm+A_LO + rr*128 + o0)   = bfpack(v.x-__bfloat162float(h0), v.y-__bfloat162float(h1));
            *(u32*)(sm+A_LO + rr*128 + o0+4) = bfpack(v.z-__bfloat162float(h2), v.w-__bfloat162float(h3));
        }
    } else {
        const float* Xin = (LAYER==1) ? g_y0 : g_y1;
        const float sc0 = g_scale[cc],   sh0 = g_shift[cc];
        const float sc1 = g_scale[cc+1], sh1 = g_shift[cc+1];
        const float sc2 = g_scale[cc+2], sh2 = g_shift[cc+2];
        const float sc3 = g_scale[cc+3], sh3 = g_shift[cc+3];
#pragma unroll 4
        for (int it2 = 0; it2 < 16; it2++) {
            int rr = rloc0 + it2*2;
            float4 v = *(const float4*)(Xin + (size_t)(m0p+rr)*64 + cc);
            float x0 = fmaxf(fmaf(v.x, sc0, sh0), 0.f);
            float x1 = fmaxf(fmaf(v.y, sc1, sh1), 0.f);
            float x2 = fmaxf(fmaf(v.z, sc2, sh2), 0.f);
            float x3 = fmaxf(fmaf(v.w, sc3, sh3), 0.f);
            u32 sw = (u32)((rr&7)<<4);
            __nv_bfloat16 h0=__float2bfloat16(x0), h1=__float2bfloat16(x1);
            __nv_bfloat16 h2=__float2bfloat16(x2), h3=__float2bfloat16(x3);
            u32 o0 = ((u32)(cc*2)) ^ sw;
            *(u32*)(sm+A_HI + rr*128 + o0)   = (u32)(*(u16*)&h0) | ((u32)(*(u16*)&h1)<<16);
            *(u32*)(sm+A_HI + rr*128 + o0+4) = (u32)(*(u16*)&h2) | ((u32)(*(u16*)&h3)<<16);
            *(u32*)(sm+A_LO + rr*128 + o0)   = bfpack(x0-__bfloat162float(h0), x1-__bfloat162float(h1));
            *(u32*)(sm+A_LO + rr*128 + o0+4) = bfpack(x2-__bfloat162float(h2), x3-__bfloat162float(h3));
        }
    }
    __syncthreads();

    // ---- mainloop (ldmatrix fragment loads) ----
    float acc[2][8][4];
#pragma unroll
    for (int mt=0; mt<2; mt++)
#pragma unroll
        for (int nt=0; nt<8; nt++)
#pragma unroll
            for (int j=0; j<4; j++) acc[mt][nt][j] = 0.f;

    const u32 sbase = s2u(sm);
    const int qr = lane>>2, qc = lane&3;
    const u32 aRowSel = (u32)(((lane>>3)&1)*8 + (lane&7));
    const u32 aKSel   = (u32)((lane>>4)*16);
    const u32 bNSel   = (u32)((lane>>4)*8 + (lane&7));
    const u32 bKSel   = (u32)(((lane>>3)&1)*16);

#pragma unroll
    for (int ks=0; ks<4; ks++) {
        const u32 kb = (u32)(ks*32);
        u32 Ah[2][4], Al[2][4];
#pragma unroll
        for (int mt=0; mt<2; mt++) {
            u32 row = (u32)(w*32 + mt*16) + aRowSel;
            u32 col = (kb + aKSel) ^ ((row&7)<<4);
            u32 adr = sbase + A_HI + row*128 + col;
            LDSM_X4(Ah[mt][0], Ah[mt][1], Ah[mt][2], Ah[mt][3], adr);
            LDSM_X4(Al[mt][0], Al[mt][1], Al[mt][2], Al[mt][3], adr + (u32)(A_LO - A_HI));
        }
#pragma unroll
        for (int ntp=0; ntp<4; ntp++) {
            u32 nrow = (u32)(ntp*16) + bNSel;
            u32 col  = (kb + bKSel) ^ ((nrow&7)<<4);
            u32 badr = sbase + B_HI + nrow*128 + col;
            u32 bh0, bh1, bh2, bh3, bl0, bl1, bl2, bl3;
            LDSM_X4(bh0, bh1, bh2, bh3, badr);
            LDSM_X4(bl0, bl1, bl2, bl3, badr + (u32)(B_LO - B_HI));
#pragma unroll
            for (int mt=0; mt<2; mt++) {
                MMA_BF16(acc[mt][2*ntp],   Ah[mt], bh0, bh1);
                MMA_BF16(acc[mt][2*ntp],   Ah[mt], bl0, bl1);
                MMA_BF16(acc[mt][2*ntp],   Al[mt], bh0, bh1);
                MMA_BF16(acc[mt][2*ntp+1], Ah[mt], bh2, bh3);
                MMA_BF16(acc[mt][2*ntp+1], Ah[mt], bl2, bl3);
                MMA_BF16(acc[mt][2*ntp+1], Al[mt], bh2, bh3);
            }
        }
    }
    __syncthreads();   // A/B smem free -> stats scratch

    // ---- epilogue: xyz add (L0), Y store (L0/L1), fused stats (+max L2) ----
    float* Ssm = (float*)sm;          // [4][64]
    float* Sqm = Ssm + 256;           // [4][64]
    const float* sdx = (const float*)(sm+DX);
    const float* Wx  = (const float*)(sm+WX);
    float* Y = (LAYER==0) ? g_y0 : g_y1;

#pragma unroll
    for (int nt=0; nt<8; nt++) {
        float y[2][4];
#pragma unroll
        for (int mt=0; mt<2; mt++)
#pragma unroll
            for (int j=0; j<4; j++) y[mt][j] = acc[mt][nt][j];
        if (LAYER == 0) {
#pragma unroll
            for (int mt=0; mt<2; mt++)
#pragma unroll
                for (int j=0; j<4; j++) {
                    int r = w*32 + mt*16 + qr + ((j>>1)<<3);
                    int ch = nt*8 + qc*2 + (j&1);
                    y[mt][j] = fmaf(sdx[r], Wx[ch],
                               fmaf(sdx[128+r], Wx[64+ch],
                               fmaf(sdx[256+r], Wx[128+ch], y[mt][j])));
                }
        }
        float s0 = y[0][0]+y[0][2]+y[1][0]+y[1][2];
        float s1 = y[0][1]+y[0][3]+y[1][1]+y[1][3];
        float q0 = y[0][0]*y[0][0]+y[0][2]*y[0][2]+y[1][0]*y[1][0]+y[1][2]*y[1][2];
        float q1 = y[0][1]*y[0][1]+y[0][3]*y[0][3]+y[1][1]*y[1][1]+y[1][3]*y[1][3];
        float mx0 = 0.f, mx1 = 0.f;
        if (LAYER == 2) {
            mx0 = fmaxf(fmaxf(y[0][0],y[0][2]), fmaxf(y[1][0],y[1][2]));
            mx1 = fmaxf(fmaxf(y[0][1],y[0][3]), fmaxf(y[1][1],y[1][3]));
        }
#pragma unroll
        for (int o=16; o>=4; o>>=1) {
            s0 += __shfl_down_sync(0xffffffffu, s0, o);
            s1 += __shfl_down_sync(0xffffffffu, s1, o);
            q0 += __shfl_down_sync(0xffffffffu, q0, o);
            q1 += __shfl_down_sync(0xffffffffu, q1, o);
            if (LAYER == 2) {
                mx0 = fmaxf(mx0, __shfl_down_sync(0xffffffffu, mx0, o));
                mx1 = fmaxf(mx1, __shfl_down_sync(0xffffffffu, mx1, o));
            }
        }
        if (lane < 4) {
            int ch = nt*8 + lane*2;
            Ssm[w*64 + ch] = s0;  Ssm[w*64 + ch + 1] = s1;
            Sqm[w*64 + ch] = q0;  Sqm[w*64 + ch + 1] = q1;
            if (LAYER == 2)
                *(float2*)(g_gmax + ((size_t)(m0p>>5) + w)*128 + n0 + ch) = make_float2(mx0, mx1);
        }
        if (LAYER != 2) {
#pragma unroll
            for (int mt=0; mt<2; mt++) {
                int r = m0p + w*32 + mt*16 + qr;
                int ch = nt*8 + qc*2;
                *(float2*)(Y + (size_t)r*64 + ch)     = make_float2(y[mt][0], y[mt][1]);
                *(float2*)(Y + (size_t)(r+8)*64 + ch) = make_float2(y[mt][2], y[mt][3]);
            }
        }
    }
    __syncthreads();
    if (t < 64) {
        float vs = Ssm[t] + Ssm[64+t] + Ssm[128+t] + Ssm[192+t];
        float vq = Sqm[t] + Sqm[64+t] + Sqm[128+t] + Sqm[192+t];
        size_t pi = (LAYER==2) ? ((size_t)blockIdx.x*128 + n0 + t)
                               : ((size_t)blockIdx.x*64 + t);
        g_parts[pi] = vs;
        g_partq[pi] = vq;
    }
}

// ============================================================================
// 4) finalize BN (unchanged)
// ============================================================================
template <int C>
__global__ __launch_bounds__(256)
void finalize_kernel(const float* __restrict__ g, const float* __restrict__ be)
{
    __shared__ double shs[256], shq[256];
    const int c = blockIdx.x, t = threadIdx.x;
    double s = 0.0, q = 0.0;
    for (int i = t; i < 4096; i += 256) {
        s += (double)g_parts[(size_t)i * C + c];
        q += (double)g_partq[(size_t)i * C + c];
    }
    shs[t] = s; shq[t] = q;
    __syncthreads();
    for (int o = 128; o; o >>= 1) {
        if (t < o) { shs[t] += shs[t+o]; shq[t] += shq[t+o]; }
        __syncthreads();
    }
    if (t == 0) {
        double mean = shs[0] / (double)Mm;
        double var  = shq[0] / (double)Mm - mean * mean;
        float sc = g[c] * (1.0f / sqrtf((float)var + 1e-5f));
        g_scale[c] = sc;
        g_shift[c] = fmaf(-(float)mean, sc, be[c]);
    }
}

// ============================================================================
// 5) output (unchanged)
// ============================================================================
__global__ __launch_bounds__(256)
void maxout_kernel(float* __restrict__ feats)
{
    int i = blockIdx.x * 256 + threadIdx.x;
    int c = i & 127;
    feats[i] = fmaxf(fmaf(g_gmax[i], g_scale[c], g_shift[c]), 0.f);
}

// ============================================================================
extern "C" void kernel_launch(void* const* d_in, const int* in_sizes, int n_in,
                              void* d_out, int out_size)
{
    const float* xyz = (const float*)d_in[0];
    const float* fea = (const float*)d_in[1];
    const float* W0  = (const float*)d_in[2];
    const float* g0  = (const float*)d_in[4];
    const float* be0 = (const float*)d_in[5];
    const float* W1  = (const float*)d_in[6];
    const float* g1  = (const float*)d_in[8];
    const float* be1 = (const float*)d_in[9];
    const float* W2  = (const float*)d_in[10];
    const float* g2  = (const float*)d_in[12];
    const float* be2 = (const float*)d_in[13];

    float* out   = (float*)d_out;
    float* samp  = out;
    float* feats = out + Bb * Ss * 3;

    const int fps_smem = Nn*16 + 2*16*8 + 16;
    const int knn_smem = Nn*16;
    const int mma_smem = 51968;

    cudaFuncSetAttribute(fps_kernel, cudaFuncAttributeMaxDynamicSharedMemorySize, fps_smem);
    cudaFuncSetAttribute(knn_kernel, cudaFuncAttributeMaxDynamicSharedMemorySize, knn_smem);
    cudaFuncSetAttribute(mma_kernel<0>, cudaFuncAttributeMaxDynamicSharedMemorySize, mma_smem);
    cudaFuncSetAttribute(mma_kernel<1>, cudaFuncAttributeMaxDynamicSharedMemorySize, mma_smem);
    cudaFuncSetAttribute(mma_kernel<2>, cudaFuncAttributeMaxDynamicSharedMemorySize, mma_smem);

    prep_kernel<<<16, 256>>>(W0, W1, W2);
    fps_kernel<<<Bb, 512, fps_smem>>>(xyz, samp);
    knn_kernel<<<dim3(Ss/16, Bb), 512, knn_smem>>>(xyz, samp);

    mma_kernel<0><<<Mm/128, 128, mma_smem>>>(fea, xyz, samp);
    finalize_kernel<64><<<64, 256>>>(g0, be0);

    mma_kernel<1><<<Mm/128, 128, mma_smem>>>(nullptr, nullptr, nullptr);
    finalize_kernel<64><<<64, 256>>>(g1, be1);

    mma_kernel<2><<<dim3(Mm/128, 2), 128, mma_smem>>>(nullptr, nullptr, nullptr);
    finalize_kernel<128><<<128, 256>>>(g2, be2);

    maxout_kernel<<<(Bb*Ss*128)/256, 256>>>(feats);
}